// round 5
// baseline (speedup 1.0000x reference)
#include <cuda_runtime.h>
#include <cuda_bf16.h>

// Cumulative mean over axis 0 of x[8192, 4096] fp32:
//   out[r, c] = (sum_{i<=r} x[i, c]) / (r + 1)
//
// Single-pass decoupled-lookback scan, tile register-resident (x read ONCE),
// with WINDOWED parallel lookback (16 predecessors per step, MLP-loaded).
//   TPB=256, each thread owns one float4 column. Tile = 8 rows x 1024 cols.
//   NCB=4 column blocks, NTILES=1024, grid=4096 (row-tile-major order).
//   Flags: 0 = none, 1 = aggregate ready, 2 = inclusive prefix ready.

#define ROWS   8192
#define COLS   4096
#define T      8
#define NTILES (ROWS / T)            // 1024
#define TPB    256
#define NCB    (COLS / (TPB * 4))    // 4
#define C4     (COLS / 4)            // 1024 float4 per row
#define WINDOW 16

// Static device scratch (no allocation allowed anywhere).
__device__ float4 g_agg[NCB * NTILES * TPB];   // 16 MB
__device__ float4 g_inc[NCB * NTILES * TPB];   // 16 MB
__device__ int    g_flag[NCB * NTILES];        // 16 KB
__device__ float  g_inv[ROWS];                 // 32 KB

__device__ __forceinline__ float4 f4_add(float4 a, float4 b) {
    a.x += b.x; a.y += b.y; a.z += b.z; a.w += b.w;
    return a;
}

__device__ __forceinline__ int ld_flag_acquire(const int* p) {
    int v;
    asm volatile("ld.global.acquire.gpu.b32 %0, [%1];" : "=r"(v) : "l"(p) : "memory");
    return v;
}
__device__ __forceinline__ void st_flag_release(int* p, int v) {
    asm volatile("st.global.release.gpu.b32 [%0], %1;" :: "l"(p), "r"(v) : "memory");
}

__global__ void k_init() {
    int i = blockIdx.x * blockDim.x + threadIdx.x;
    if (i < ROWS) g_inv[i] = 1.0f / (float)(i + 1);
    if (i < NCB * NTILES) g_flag[i] = 0;
}

__global__ void __launch_bounds__(TPB, 4)
k_scan(const float* __restrict__ x, float* __restrict__ out) {
    const int bx  = blockIdx.x;
    const int rt  = bx / NCB;              // row tile (low tiles dispatch first)
    const int cb  = bx % NCB;              // column block
    const int tid = threadIdx.x;

    const float4* __restrict__ x4 = reinterpret_cast<const float4*>(x);
    float4*       __restrict__ o4 = reinterpret_cast<float4*>(out);

    const int col4 = cb * TPB + tid;
    const int base = rt * T * C4 + col4;

    // ---- Phase 1: load tile into registers, compute aggregate --------------
    float4 v[T];
#pragma unroll
    for (int r = 0; r < T; r++) v[r] = __ldg(&x4[base + r * C4]);

    float4 agg = v[0];
#pragma unroll
    for (int r = 1; r < T; r++) agg = f4_add(agg, v[r]);

    const int sidx = cb * NTILES + rt;
    g_agg[sidx * TPB + tid] = agg;
    __syncthreads();                       // all payload stores issued (cta scope)
    if (tid == 0) {
        __threadfence();                   // make payload visible at gpu scope
        st_flag_release(&g_flag[sidx], 1);
    }

    // ---- Windowed decoupled lookback ---------------------------------------
    float4 prefix = make_float4(0.f, 0.f, 0.f, 0.f);
    __shared__ int s_flags[WINDOW];

    for (int p = rt - 1; p >= 0; ) {
        const int W = (p + 1 < WINDOW) ? (p + 1) : WINDOW;

        // Threads 0..W-1 poll W predecessor flags concurrently.
        if (tid < W) {
            const int* fp = &g_flag[cb * NTILES + (p - tid)];
            int f = ld_flag_acquire(fp);
            while (f == 0) { __nanosleep(64); f = ld_flag_acquire(fp); }
            s_flags[tid] = f;
        }
        __syncthreads();

        // Cut at the nearest predecessor with an inclusive prefix (flag=2).
        int  cut = W;
        bool have_inc = false;
        for (int j = 0; j < W; j++) {
            if (s_flags[j] == 2) { cut = j; have_inc = true; break; }
        }

        // Accumulate 'cut' aggregates with independent (MLP) loads.
        float4 acc = make_float4(0.f, 0.f, 0.f, 0.f);
#pragma unroll 4
        for (int j = 0; j < cut; j++) {
            acc = f4_add(acc, __ldcg(&g_agg[(cb * NTILES + p - j) * TPB + tid]));
        }
        if (have_inc) {
            acc = f4_add(acc, __ldcg(&g_inc[(cb * NTILES + p - cut) * TPB + tid]));
        }
        prefix = f4_add(prefix, acc);

        __syncthreads();                   // protect s_flags before reuse
        if (have_inc) break;
        p -= W;
    }

    // ---- Publish inclusive prefix ASAP (before output stores) --------------
    g_inc[sidx * TPB + tid] = f4_add(prefix, agg);
    __syncthreads();
    if (tid == 0) {
        __threadfence();
        st_flag_release(&g_flag[sidx], 2);
    }

    // ---- Phase 2: scan registers, scale, store (no re-read of x) -----------
    float4 run = prefix;
#pragma unroll
    for (int r = 0; r < T; r++) {
        run = f4_add(run, v[r]);
        const float inv = __ldg(&g_inv[rt * T + r]);   // warp-uniform, L1-hit
        float4 o;
        o.x = run.x * inv; o.y = run.y * inv;
        o.z = run.z * inv; o.w = run.w * inv;
        o4[base + r * C4] = o;
    }
}

extern "C" void kernel_launch(void* const* d_in, const int* in_sizes, int n_in,
                              void* d_out, int out_size) {
    const float* x   = (const float*)d_in[0];
    float*       out = (float*)d_out;

    k_init<<<(ROWS + 255) / 256, 256>>>();
    k_scan<<<NTILES * NCB, TPB>>>(x, out);
}

// round 6
// speedup vs baseline: 1.0523x; 1.0523x over previous
#include <cuda_runtime.h>
#include <cuda_bf16.h>

// Cumulative mean over axis 0 of x[8192, 4096] fp32:
//   out[r, c] = (sum_{i<=r} x[i, c]) / (r + 1)
//
// Bandwidth-tuned 3-pass scan (no inter-block sync):
//   k_partial : per-tile column sums -> g_part  (reads x once; also fills g_inv)
//   k_scan    : in-place inclusive scan of g_part over tiles (L2-resident)
//   k_final   : out = (excl prefix + tile scan) * inv  (reads x once, writes out)

#define ROWS   8192
#define COLS   4096
#define T      16
#define NTILES (ROWS / T)            // 512
#define TPB    256
#define NCB    (COLS / (TPB * 4))    // 4 column blocks (1024 cols each)
#define C4     (COLS / 4)            // 1024 float4 per row

// Static device scratch (no allocation allowed anywhere).
__device__ float4 g_part[NTILES * C4];   // [tile][col4], 8 MB
__device__ float  g_inv[ROWS];           // 1/(r+1), 32 KB

__device__ __forceinline__ float4 f4_add(float4 a, float4 b) {
    a.x += b.x; a.y += b.y; a.z += b.z; a.w += b.w;
    return a;
}

// ---------------- Pass 1: per-tile partial sums (+ inv table) ----------------
__global__ void __launch_bounds__(TPB)
k_partial(const float* __restrict__ x) {
    const int bx  = blockIdx.x;
    const int rt  = bx / NCB;
    const int cb  = bx % NCB;
    const int tid = threadIdx.x;

    // Fill the reciprocal table from the first 8192 threads (one elem each).
    const int gt = bx * TPB + tid;
    if (gt < ROWS) g_inv[gt] = 1.0f / (float)(gt + 1);

    const float4* __restrict__ x4 = reinterpret_cast<const float4*>(x);
    const int col4 = cb * TPB + tid;
    const int base = rt * T * C4 + col4;

    // 16 independent loads, 4 independent accumulators (MLP ~16).
    float4 a0 = make_float4(0.f, 0.f, 0.f, 0.f);
    float4 a1 = a0, a2 = a0, a3 = a0;
#pragma unroll
    for (int r = 0; r < T; r += 4) {
        float4 v0 = __ldg(&x4[base + (r + 0) * C4]);
        float4 v1 = __ldg(&x4[base + (r + 1) * C4]);
        float4 v2 = __ldg(&x4[base + (r + 2) * C4]);
        float4 v3 = __ldg(&x4[base + (r + 3) * C4]);
        a0 = f4_add(a0, v0);
        a1 = f4_add(a1, v1);
        a2 = f4_add(a2, v2);
        a3 = f4_add(a3, v3);
    }
    g_part[rt * C4 + col4] = f4_add(f4_add(a0, a1), f4_add(a2, a3));
}

// ---------------- Pass 2: scan partials over tiles (in place, L2) ------------
__global__ void __launch_bounds__(128)
k_scan() {
    const int t = blockIdx.x * 128 + threadIdx.x;   // 0..1023, one col4 each
    float4 run = make_float4(0.f, 0.f, 0.f, 0.f);
#pragma unroll 8
    for (int rt = 0; rt < NTILES; rt++) {
        const int idx = rt * C4 + t;
        run = f4_add(run, g_part[idx]);
        g_part[idx] = run;                           // inclusive prefix
    }
}

// ---------------- Pass 3: final scan + scale + store -------------------------
__global__ void __launch_bounds__(TPB)
k_final(const float* __restrict__ x, float* __restrict__ out) {
    const int bx  = blockIdx.x;
    const int rt  = bx / NCB;
    const int cb  = bx % NCB;
    const int tid = threadIdx.x;

    const float4* __restrict__ x4 = reinterpret_cast<const float4*>(x);
    float4*       __restrict__ o4 = reinterpret_cast<float4*>(out);
    const int col4 = cb * TPB + tid;
    const int base = rt * T * C4 + col4;

    // Exclusive prefix for this tile = inclusive prefix of tile rt-1.
    float4 run = (rt == 0) ? make_float4(0.f, 0.f, 0.f, 0.f)
                           : __ldg(&g_part[(rt - 1) * C4 + col4]);

    // Front-load the whole tile (MLP = 16 independent LDG.128).
    float4 v[T];
#pragma unroll
    for (int r = 0; r < T; r++) v[r] = __ldg(&x4[base + r * C4]);

#pragma unroll
    for (int r = 0; r < T; r++) {
        run = f4_add(run, v[r]);
        const float inv = __ldg(&g_inv[rt * T + r]);   // warp-uniform, cached
        float4 o;
        o.x = run.x * inv; o.y = run.y * inv;
        o.z = run.z * inv; o.w = run.w * inv;
        o4[base + r * C4] = o;
    }
}

extern "C" void kernel_launch(void* const* d_in, const int* in_sizes, int n_in,
                              void* d_out, int out_size) {
    const float* x   = (const float*)d_in[0];
    float*       out = (float*)d_out;

    k_partial<<<NTILES * NCB, TPB>>>(x);
    k_scan<<<C4 / 128, 128>>>();
    k_final<<<NTILES * NCB, TPB>>>(x, out);
}